// round 4
// baseline (speedup 1.0000x reference)
#include <cuda_runtime.h>
#include <cuda_fp16.h>

#define NN    30000
#define DD    32
#define HH    128
#define KD    10
#define AP    144      // A row pitch (floats)
#define NPAD  30080    // 235 * 128

typedef unsigned long long ull;

__device__ __forceinline__ ull pack2(float a, float b) {
    ull r; asm("mov.b64 %0, {%1, %2};" : "=l"(r) : "f"(a), "f"(b)); return r;
}
__device__ __forceinline__ ull fma2(ull a, ull b, ull c) {
    ull d; asm("fma.rn.f32x2 %0, %1, %2, %3;" : "=l"(d) : "l"(a), "l"(b), "l"(c)); return d;
}
__device__ __forceinline__ float2 unpk(ull v) {
    float2 r; asm("mov.b64 {%0, %1}, %2;" : "=f"(r.x), "=f"(r.y) : "l"(v)); return r;
}

__device__ float  g_c[HH];              // relu(Wt4) @ Wt3
__device__ float  g_bsum[HH];           // b0 + b1 + b2
__device__ __half g_feat[NN * HH];      // fp16 feature cache (7.68 MB, L2-resident)
__device__ float  g_A[NPAD * AP];       // augmented A matrix scratch (zero-init)

// ---------------------------------------------------------------- prep
__global__ void prep_kernel(const float* __restrict__ Wt3,
                            const float* __restrict__ Wt4,
                            const float* __restrict__ b0,
                            const float* __restrict__ b1,
                            const float* __restrict__ b2) {
    int j = threadIdx.x;
    float acc = 0.f;
#pragma unroll 8
    for (int h = 0; h < HH; ++h) {
        float r = Wt4[h];
        r = r > 0.f ? r : 0.f;
        acc += r * Wt3[h * HH + j];
    }
    g_c[j] = acc;
    g_bsum[j] = b0[j] + b1[j] + b2[j];
}

// ---------------------------------------------------------------- fp32 -> fp16 feature
__global__ void convert_kernel(const float* __restrict__ f) {
    int i = blockIdx.x * 256 + threadIdx.x;        // one float4 per thread
    float4 v = ((const float4*)f)[i];
    __half2 h0 = __float22half2_rn(make_float2(v.x, v.y));
    __half2 h1 = __float22half2_rn(make_float2(v.z, v.w));
    uint2 o;
    o.x = *(unsigned*)&h0;
    o.y = *(unsigned*)&h1;
    ((uint2*)g_feat)[i] = o;
}

// ---------------------------------------------------------------- gather: 1 warp / node
__global__ void __launch_bounds__(256, 3)
gather_kernel(const float* __restrict__ x,  const float* __restrict__ label,
              const float* __restrict__ w,  const float* __restrict__ et,
              const int*   __restrict__ src) {
    __shared__ float2 meta[8][DD];                 // (e, src-as-float) per warp
    const int wp = threadIdx.x >> 5, lane = threadIdx.x & 31;
    const int n  = blockIdx.x * 8 + wp;            // grid*8 == 30000 exactly

    const int base = n * DD + lane;
    int   s_l = src[base];                         // coalesced
    float e_l = et[2 * base];                      // stride-2
    float S   = w[base] * e_l;
#pragma unroll
    for (int o = 16; o; o >>= 1) S += __shfl_xor_sync(0xffffffffu, S, o);
    meta[wp][lane] = make_float2(e_l, __int_as_float(s_l));
    __syncwarp();

    const uint2* fp = (const uint2*)g_feat;        // 32 uint2 per row (256B)
    float2 a0 = make_float2(0.f, 0.f), a1 = make_float2(0.f, 0.f);
#pragma unroll
    for (int d = 0; d < DD; ++d) {
        float2 me = meta[wp][d];                   // LDS.64 broadcast
        int   s = __float_as_int(me.y);
        float e = me.x;
        uint2 q = __ldg(fp + s * (HH / 4) + lane); // LDG.64, 256B/row coalesced
        __half2 h0 = *(__half2*)&q.x;
        __half2 h1 = *(__half2*)&q.y;
        float2 f0 = __half22float2(h0);
        float2 f1 = __half22float2(h1);
        a0.x += f0.x * e; a0.y += f0.y * e;
        a1.x += f1.x * e; a1.y += f1.y * e;
    }

    float* Ar = g_A + n * AP;
    ((float4*)Ar)[lane] = make_float4(a0.x, a0.y, a1.x, a1.y);   // 512B coalesced
    if (lane == 0) Ar[140] = S;
    if (lane < 2)  Ar[128 + lane] = x[n * 2 + lane];
    if (lane < KD) Ar[130 + lane] = label[n * KD + lane];
}

// ---------------------------------------------------------------- GEMM: relu(A@B + bsum)
// thread tile: 4 rows x 8 cols.  jb = (tid&15)*8, mb = (tid>>4)*4.
__device__ __forceinline__ void gstep(const float* __restrict__ brow,
                                      const float* __restrict__ Abase,
                                      int k, int jb, ull acc[4][4]) {
    union { float4 f; ull v[2]; } b0, b1;
    b0.f = __ldg((const float4*)(brow + jb));
    b1.f = __ldg((const float4*)(brow + jb) + 1);
#pragma unroll
    for (int i = 0; i < 4; ++i) {
        float a = __ldg(Abase + i * AP + k);       // half-warp broadcast, L1-hit
        ull a2 = pack2(a, a);
        acc[i][0] = fma2(a2, b0.v[0], acc[i][0]);
        acc[i][1] = fma2(a2, b0.v[1], acc[i][1]);
        acc[i][2] = fma2(a2, b1.v[0], acc[i][2]);
        acc[i][3] = fma2(a2, b1.v[1], acc[i][3]);
    }
}

__global__ void __launch_bounds__(512, 2)
gemm_kernel(const float* __restrict__ W0, const float* __restrict__ W1,
            const float* __restrict__ W2, float* __restrict__ out) {
    const int tid = threadIdx.x;
    const int jb  = (tid & 15) * 8;
    const int mb  = (tid >> 4) * 4;
    const int n0  = blockIdx.x * 128;
    const float* Abase = g_A + (n0 + mb) * AP;

    ull acc[4][4];
    {
        union { float4 f; ull v[2]; } i0, i1;
        i0.f = __ldg((const float4*)(g_bsum + jb));
        i1.f = __ldg((const float4*)(g_bsum + jb) + 1);
#pragma unroll
        for (int i = 0; i < 4; ++i) {
            acc[i][0] = i0.v[0]; acc[i][1] = i0.v[1];
            acc[i][2] = i1.v[0]; acc[i][3] = i1.v[1];
        }
    }

#pragma unroll 4
    for (int k = 0; k < HH; ++k) gstep(W2 + k * HH, Abase, k, jb, acc);
    gstep(W0,      Abase, 128, jb, acc);
    gstep(W0 + HH, Abase, 129, jb, acc);
#pragma unroll
    for (int k = 0; k < KD; ++k) gstep(W1 + k * HH, Abase, 130 + k, jb, acc);
    gstep(g_c, Abase, 140, jb, acc);

#pragma unroll
    for (int i = 0; i < 4; ++i) {
        int n = n0 + mb + i;
        if (n < NN) {
            float2 q0 = unpk(acc[i][0]), q1 = unpk(acc[i][1]);
            float2 q2 = unpk(acc[i][2]), q3 = unpk(acc[i][3]);
            float4 r0, r1;
            r0.x = fmaxf(q0.x, 0.f); r0.y = fmaxf(q0.y, 0.f);
            r0.z = fmaxf(q1.x, 0.f); r0.w = fmaxf(q1.y, 0.f);
            r1.x = fmaxf(q2.x, 0.f); r1.y = fmaxf(q2.y, 0.f);
            r1.z = fmaxf(q3.x, 0.f); r1.w = fmaxf(q3.y, 0.f);
            ((float4*)(out + n * HH + jb))[0] = r0;
            ((float4*)(out + n * HH + jb))[1] = r1;
        }
    }
}

// ---------------------------------------------------------------- launch
extern "C" void kernel_launch(void* const* d_in, const int* in_sizes, int n_in,
                              void* d_out, int out_size) {
    const float* feature = (const float*)d_in[0];
    const float* x       = (const float*)d_in[1];
    const float* label   = (const float*)d_in[2];
    const float* w       = (const float*)d_in[3];
    const float* et      = (const float*)d_in[4];
    const int*   src     = (const int*)  d_in[5];
    const float* W0      = (const float*)d_in[6];
    const float* b0      = (const float*)d_in[7];
    const float* W1      = (const float*)d_in[8];
    const float* b1      = (const float*)d_in[9];
    const float* W2      = (const float*)d_in[10];
    const float* b2      = (const float*)d_in[11];
    const float* Wt3     = (const float*)d_in[12];
    const float* Wt4     = (const float*)d_in[13];
    float* out = (float*)d_out;

    prep_kernel<<<1, HH>>>(Wt3, Wt4, b0, b1, b2);
    convert_kernel<<<(NN * HH / 4) / 256, 256>>>(feature);     // 3750 blocks
    gather_kernel<<<NN / 8, 256>>>(x, label, w, et, src);      // 3750 blocks
    gemm_kernel<<<NPAD / 128, 512>>>(W0, W1, W2, out);         // 235 blocks
}

// round 6
// speedup vs baseline: 1.9389x; 1.9389x over previous
#include <cuda_runtime.h>
#include <cuda_fp16.h>

#define NN    30000
#define DD    32
#define HH    128
#define KD    10
#define AP    144      // A row pitch (floats), == padded K
#define KTOT  144      // 128 n1h + 2 x + 10 label + 1 S + 3 zero-pad
#define KC    48       // K chunk
#define NPAD  30080    // 235 * 128
#define ASP   49       // As smem row pitch (conflict-free A broadcast)

#define GEMM_SMEM ((128 * ASP + KC * HH) * 4)   // 49664 bytes

typedef unsigned long long ull;

__device__ __forceinline__ ull pack2(float a, float b) {
    ull r; asm("mov.b64 %0, {%1, %2};" : "=l"(r) : "f"(a), "f"(b)); return r;
}
__device__ __forceinline__ ull fma2(ull a, ull b, ull c) {
    ull d; asm("fma.rn.f32x2 %0, %1, %2, %3;" : "=l"(d) : "l"(a), "l"(b), "l"(c)); return d;
}
__device__ __forceinline__ float2 unpk(ull v) {
    float2 r; asm("mov.b64 {%0, %1}, %2;" : "=f"(r.x), "=f"(r.y) : "l"(v)); return r;
}

__device__ float  g_B[KTOT * HH];       // assembled B matrix [144][128]
__device__ float  g_bsum[HH];           // b0 + b1 + b2
__device__ __half g_feat[NN * HH];      // fp16 feature cache (7.68 MB, L2-resident)
__device__ float  g_A[NPAD * AP];       // augmented A (row-major); cols 141-143 stay 0

// ------------------------------------------------- prep: build g_B + g_bsum
__global__ void prep_kernel(const float* __restrict__ W0, const float* __restrict__ b0,
                            const float* __restrict__ W1, const float* __restrict__ b1,
                            const float* __restrict__ W2, const float* __restrict__ b2,
                            const float* __restrict__ Wt3, const float* __restrict__ Wt4) {
    int r = blockIdx.x, j = threadIdx.x;
    float v = 0.f;
    if (r < 128)                 v = W2[r * HH + j];
    else if (r < 130)            v = W0[(r - 128) * HH + j];
    else if (r < 140)            v = W1[(r - 130) * HH + j];
    else if (r == 140) {         // c = relu(Wt4) @ Wt3
        float acc = 0.f;
#pragma unroll 8
        for (int h = 0; h < HH; ++h) {
            float t = Wt4[h];
            t = t > 0.f ? t : 0.f;
            acc += t * Wt3[h * HH + j];
        }
        v = acc;
    }                            // rows 141-143: v = 0
    g_B[r * HH + j] = v;
    if (r == 0) g_bsum[j] = b0[j] + b1[j] + b2[j];
}

// ------------------------------------------------- fp32 -> fp16 feature
__global__ void convert_kernel(const float* __restrict__ f) {
    int i = blockIdx.x * 256 + threadIdx.x;        // one float4 per thread
    float4 v = ((const float4*)f)[i];
    __half2 h0 = __float22half2_rn(make_float2(v.x, v.y));
    __half2 h1 = __float22half2_rn(make_float2(v.z, v.w));
    uint2 o;
    o.x = *(unsigned*)&h0;
    o.y = *(unsigned*)&h1;
    ((uint2*)g_feat)[i] = o;
}

// ------------------------------------------------- gather: 1 warp / node
__global__ void __launch_bounds__(256, 3)
gather_kernel(const float* __restrict__ x,  const float* __restrict__ label,
              const float* __restrict__ w,  const float* __restrict__ et,
              const int*   __restrict__ src) {
    __shared__ float2 meta[8][DD];
    const int wp = threadIdx.x >> 5, lane = threadIdx.x & 31;
    const int n  = blockIdx.x * 8 + wp;            // 3750 * 8 == 30000

    const int base = n * DD + lane;
    int   s_l = src[base];
    float e_l = ((const float2*)et)[base].x;       // et[...,0]
    float S   = w[base] * e_l;
#pragma unroll
    for (int o = 16; o; o >>= 1) S += __shfl_xor_sync(0xffffffffu, S, o);
    meta[wp][lane] = make_float2(e_l, __int_as_float(s_l));
    __syncwarp();

    const uint2* fp = (const uint2*)g_feat;        // 32 uint2 per row (256B)
    float2 a0 = make_float2(0.f, 0.f), a1 = make_float2(0.f, 0.f);
#pragma unroll
    for (int d = 0; d < DD; ++d) {
        float2 me = meta[wp][d];
        int   s = __float_as_int(me.y);
        float e = me.x;
        uint2 q = __ldg(fp + s * (HH / 4) + lane);
        float2 f0 = __half22float2(*(__half2*)&q.x);
        float2 f1 = __half22float2(*(__half2*)&q.y);
        a0.x += f0.x * e; a0.y += f0.y * e;
        a1.x += f1.x * e; a1.y += f1.y * e;
    }

    float* Ar = g_A + n * AP;
    ((float4*)Ar)[lane] = make_float4(a0.x, a0.y, a1.x, a1.y);
    if (lane == 0) Ar[140] = S;
    if (lane < 2)  Ar[128 + lane] = x[n * 2 + lane];
    if (lane < KD) Ar[130 + lane] = label[n * KD + lane];
}

// ------------------------------------------------- GEMM: relu(A[128xK] @ B[Kx128] + bsum)
// 256 threads, thread tile 8m x 8j, smem-chunked K (3 x 48), dynamic smem.
__global__ void __launch_bounds__(256, 2)
gemm_kernel(float* __restrict__ out) {
    extern __shared__ float smem[];
    float* As = smem;                   // [128 m][49]
    float* Bs = smem + 128 * ASP;       // [48 k][128 j]

    const int tid  = threadIdx.x;
    const int jb   = (tid & 15) * 8;
    const int mb   = (tid >> 4) * 8;
    const int n0   = blockIdx.x * 128;

    ull acc[8][4];
    {
        union { float4 f; ull v[2]; } i0, i1;
        i0.f = *(const float4*)(g_bsum + jb);
        i1.f = *(const float4*)(g_bsum + jb + 4);
#pragma unroll
        for (int i = 0; i < 8; ++i) {
            acc[i][0] = i0.v[0]; acc[i][1] = i0.v[1];
            acc[i][2] = i1.v[0]; acc[i][3] = i1.v[1];
        }
    }

    for (int c = 0; c < KTOT / KC; ++c) {
        // stage As: 128 rows x 48 floats = 1536 float4
#pragma unroll
        for (int t = 0; t < 6; ++t) {
            int i   = t * 256 + tid;
            int row = i / 12, q = i % 12;
            float4 v = __ldg((const float4*)(g_A + (n0 + row) * AP + c * KC) + q);
            float* d = As + row * ASP + q * 4;
            d[0] = v.x; d[1] = v.y; d[2] = v.z; d[3] = v.w;
        }
        // stage Bs: 48 x 128 = 1536 float4
#pragma unroll
        for (int t = 0; t < 6; ++t) {
            int i = t * 256 + tid;
            ((float4*)Bs)[i] = __ldg((const float4*)g_B + c * (KC * HH / 4) + i);
        }
        __syncthreads();

#pragma unroll 8
        for (int k = 0; k < KC; ++k) {
            union { float4 f; ull v[2]; } b0, b1;
            b0.f = *(const float4*)(Bs + k * HH + jb);
            b1.f = *(const float4*)(Bs + k * HH + jb + 4);
#pragma unroll
            for (int i = 0; i < 8; ++i) {
                float a = As[(mb + i) * ASP + k];
                ull a2 = pack2(a, a);
                acc[i][0] = fma2(a2, b0.v[0], acc[i][0]);
                acc[i][1] = fma2(a2, b0.v[1], acc[i][1]);
                acc[i][2] = fma2(a2, b1.v[0], acc[i][2]);
                acc[i][3] = fma2(a2, b1.v[1], acc[i][3]);
            }
        }
        __syncthreads();
    }

#pragma unroll
    for (int i = 0; i < 8; ++i) {
        int n = n0 + mb + i;
        if (n < NN) {
            float2 q0 = unpk(acc[i][0]), q1 = unpk(acc[i][1]);
            float2 q2 = unpk(acc[i][2]), q3 = unpk(acc[i][3]);
            float4 r0, r1;
            r0.x = fmaxf(q0.x, 0.f); r0.y = fmaxf(q0.y, 0.f);
            r0.z = fmaxf(q1.x, 0.f); r0.w = fmaxf(q1.y, 0.f);
            r1.x = fmaxf(q2.x, 0.f); r1.y = fmaxf(q2.y, 0.f);
            r1.z = fmaxf(q3.x, 0.f); r1.w = fmaxf(q3.y, 0.f);
            ((float4*)(out + n * HH + jb))[0] = r0;
            ((float4*)(out + n * HH + jb))[1] = r1;
        }
    }
}

// ------------------------------------------------- launch
extern "C" void kernel_launch(void* const* d_in, const int* in_sizes, int n_in,
                              void* d_out, int out_size) {
    const float* feature = (const float*)d_in[0];
    const float* x       = (const float*)d_in[1];
    const float* label   = (const float*)d_in[2];
    const float* w       = (const float*)d_in[3];
    const float* et      = (const float*)d_in[4];
    const int*   src     = (const int*)  d_in[5];
    const float* W0      = (const float*)d_in[6];
    const float* b0      = (const float*)d_in[7];
    const float* W1      = (const float*)d_in[8];
    const float* b1      = (const float*)d_in[9];
    const float* W2      = (const float*)d_in[10];
    const float* b2      = (const float*)d_in[11];
    const float* Wt3     = (const float*)d_in[12];
    const float* Wt4     = (const float*)d_in[13];
    float* out = (float*)d_out;

    cudaFuncSetAttribute(gemm_kernel, cudaFuncAttributeMaxDynamicSharedMemorySize,
                         GEMM_SMEM);

    prep_kernel<<<KTOT, HH>>>(W0, b0, W1, b1, W2, b2, Wt3, Wt4);
    convert_kernel<<<(NN * HH / 4) / 256, 256>>>(feature);     // 3750 blocks
    gather_kernel<<<NN / 8, 256>>>(x, label, w, et, src);      // 3750 blocks
    gemm_kernel<<<NPAD / 128, 256, GEMM_SMEM>>>(out);          // 235 blocks
}